// round 4
// baseline (speedup 1.0000x reference)
#include <cuda_runtime.h>

#define BB 32
#define TT 512
#define DENC 512
#define HH 640
#define EE 640
#define JJ 640
#define VV 4096
#define G4 2560   // 4*H

// ---------------- scratch (static device allocations, allowed) ----------------
__device__ float d_xt[BB * EE];
__device__ float d_gates[BB * G4];
__device__ float d_h0[BB * HH];
__device__ float d_c0[BB * HH];
__device__ float d_h1[BB * HH];
__device__ float d_c1[BB * HH];
__device__ float d_gvec[BB * JJ];
__device__ float d_f[BB * TT * JJ];   // 16384 x 640  (~42 MB)

__device__ __forceinline__ float sigmoidf(float x) {
    return 1.0f / (1.0f + expf(-x));
}

// ---------------- embedding lookup (targets stored as int32) ----------------
__global__ void embed_k(const int* __restrict__ targets,
                        const float* __restrict__ embw) {
    int i = blockIdx.x * blockDim.x + threadIdx.x;  // B*E
    if (i >= BB * EE) return;
    int b = i / EE, e = i % EE;
    int tok = targets[b];                 // (B,1) int32
    if (tok < 0 || tok >= VV) tok = 0;    // defensive clamp (no crash on dtype surprise)
    d_xt[i] = embw[(size_t)tok * EE + e];
}

// ---------------- LSTM gates ----------------
// gates[b][j] = x.Wih[j] + h.Whh[j] + bih[j] + bhh[j]
// layer==0: x = d_xt ;  layer==1: x = d_h0.  hprev from input states.
__global__ void gates_k(int layer, const float* __restrict__ hprev,
                        const float* __restrict__ wih, const float* __restrict__ whh,
                        const float* __restrict__ bih, const float* __restrict__ bhh) {
    int b = blockIdx.y;
    int j = blockIdx.x * 128 + threadIdx.x;
    const float* x = (layer == 0) ? d_xt : d_h0;
    __shared__ float4 sx[EE / 4];
    __shared__ float4 sh[HH / 4];
    for (int i = threadIdx.x; i < EE / 4; i += 128)
        sx[i] = ((const float4*)(x + (size_t)b * EE))[i];
    for (int i = threadIdx.x; i < HH / 4; i += 128)
        sh[i] = ((const float4*)(hprev + (size_t)b * HH))[i];
    __syncthreads();

    const float4* wi = (const float4*)(wih + (size_t)j * EE);
    const float4* wh = (const float4*)(whh + (size_t)j * HH);
    float acc = bih[j] + bhh[j];
#pragma unroll 4
    for (int k = 0; k < EE / 4; k++) {
        float4 w = wi[k], v = sx[k];
        acc += w.x * v.x + w.y * v.y + w.z * v.z + w.w * v.w;
    }
#pragma unroll 4
    for (int k = 0; k < HH / 4; k++) {
        float4 w = wh[k], v = sh[k];
        acc += w.x * v.x + w.y * v.y + w.z * v.z + w.w * v.w;
    }
    d_gates[(size_t)b * G4 + j] = acc;
}

// ---------------- LSTM pointwise ----------------
__global__ void lstm_pw_k(int layer, const float* __restrict__ cprev) {
    int i = blockIdx.x * blockDim.x + threadIdx.x;  // B*H
    if (i >= BB * HH) return;
    int b = i / HH;
    int j = i % HH;
    const float* gr = d_gates + (size_t)b * G4;
    float ig = sigmoidf(gr[j]);
    float fg = sigmoidf(gr[HH + j]);
    float gg = tanhf(gr[2 * HH + j]);
    float og = sigmoidf(gr[3 * HH + j]);
    float c = fg * cprev[i] + ig * gg;
    float h = og * tanhf(c);
    if (layer == 0) { d_c0[i] = c; d_h0[i] = h; }
    else            { d_c1[i] = c; d_h1[i] = h; }
}

// ---------------- pred head: g[b][j] = h1 . Wp[j] + pb[j] ----------------
__global__ void pred_k(const float* __restrict__ wp, const float* __restrict__ pb) {
    int b = blockIdx.y;
    int j = blockIdx.x * 128 + threadIdx.x;  // grid.x = J/128 = 5
    __shared__ float4 sh[HH / 4];
    for (int i = threadIdx.x; i < HH / 4; i += 128)
        sh[i] = ((const float4*)(d_h1 + (size_t)b * HH))[i];
    __syncthreads();
    const float4* w = (const float4*)(wp + (size_t)j * HH);
    float acc = pb[j];
#pragma unroll 4
    for (int k = 0; k < HH / 4; k++) {
        float4 ww = w[k], v = sh[k];
        acc += ww.x * v.x + ww.y * v.y + ww.z * v.z + ww.w * v.w;
    }
    d_gvec[(size_t)b * JJ + j] = acc;
}

// ---------------- f GEMM: f[m][n] = sum_k enc[b][k][t] * Wenc[n][k] + encb[n]
// M=16384 (m=b*512+t), N=640, K=512.  BM=128 BN=64 BK=16, 256 thr, 8x4/thr.
__global__ void __launch_bounds__(256) fgemm_k(const float* __restrict__ enc,
                                               const float* __restrict__ wenc,
                                               const float* __restrict__ encb) {
    __shared__ float As[16][128];
    __shared__ float Bs[16][64];
    int m0 = blockIdx.x * 128;
    int n0 = blockIdx.y * 64;
    int b = m0 / TT;
    int t0 = m0 % TT;
    int tid = threadIdx.x;
    int tx = tid % 16, ty = tid / 16;

    const float* encB = enc + (size_t)b * DENC * TT;
    float acc[8][4];
#pragma unroll
    for (int i = 0; i < 8; i++)
#pragma unroll
        for (int j = 0; j < 4; j++) acc[i][j] = 0.f;

    int kl = tid >> 5;            // 0..7
    int mv = (tid & 31) << 2;     // 0..124
    int nn = tid >> 2;            // 0..63
    int kv = (tid & 3) << 2;      // 0,4,8,12

    for (int k0 = 0; k0 < DENC; k0 += 16) {
#pragma unroll
        for (int r = 0; r < 2; r++) {
            int kk = kl + r * 8;
            float4 v = *(const float4*)(encB + (size_t)(k0 + kk) * TT + t0 + mv);
            *(float4*)(&As[kk][mv]) = v;
        }
        {
            float4 w = *(const float4*)(wenc + (size_t)(n0 + nn) * DENC + k0 + kv);
            Bs[kv + 0][nn] = w.x;
            Bs[kv + 1][nn] = w.y;
            Bs[kv + 2][nn] = w.z;
            Bs[kv + 3][nn] = w.w;
        }
        __syncthreads();
#pragma unroll
        for (int k = 0; k < 16; k++) {
            float4 a0 = *(float4*)(&As[k][ty * 8]);
            float4 a1 = *(float4*)(&As[k][ty * 8 + 4]);
            float4 bb = *(float4*)(&Bs[k][tx * 4]);
            float a[8] = {a0.x, a0.y, a0.z, a0.w, a1.x, a1.y, a1.z, a1.w};
            float bv[4] = {bb.x, bb.y, bb.z, bb.w};
#pragma unroll
            for (int i = 0; i < 8; i++)
#pragma unroll
                for (int j = 0; j < 4; j++) acc[i][j] = fmaf(a[i], bv[j], acc[i][j]);
        }
        __syncthreads();
    }
    float4 eb = *(const float4*)(encb + n0 + tx * 4);
#pragma unroll
    for (int i = 0; i < 8; i++) {
        float4 o;
        o.x = acc[i][0] + eb.x;
        o.y = acc[i][1] + eb.y;
        o.z = acc[i][2] + eb.z;
        o.w = acc[i][3] + eb.w;
        *(float4*)(&d_f[(size_t)(m0 + ty * 8 + i) * JJ + n0 + tx * 4]) = o;
    }
}

// ---------------- out GEMM: out[m][v] = sum_k relu(f[m][k]+g[b][k]) * Wout[v][k] + ob[v]
// M=16384, N=4096, K=640.  BM=128 BN=64 BK=16.  Bounds-guarded stores.
__global__ void __launch_bounds__(256) outgemm_k(const float* __restrict__ wout,
                                                 const float* __restrict__ outb,
                                                 float* __restrict__ out,
                                                 long long out_elems) {
    __shared__ float As[16][128];
    __shared__ float Bs[16][64];
    int m0 = blockIdx.x * 128;
    int n0 = blockIdx.y * 64;
    int b = m0 / TT;
    int tid = threadIdx.x;
    int tx = tid % 16, ty = tid / 16;
    const float* grow = d_gvec + (size_t)b * JJ;

    float acc[8][4];
#pragma unroll
    for (int i = 0; i < 8; i++)
#pragma unroll
        for (int j = 0; j < 4; j++) acc[i][j] = 0.f;

    int row = tid >> 2;         // 0..63
    int kv = (tid & 3) << 2;    // 0,4,8,12

    for (int k0 = 0; k0 < JJ; k0 += 16) {
        float4 gg = *(const float4*)(grow + k0 + kv);
#pragma unroll
        for (int r = 0; r < 2; r++) {
            int mm = row + r * 64;
            float4 v = *(const float4*)(d_f + (size_t)(m0 + mm) * JJ + k0 + kv);
            As[kv + 0][mm] = fmaxf(v.x + gg.x, 0.f);
            As[kv + 1][mm] = fmaxf(v.y + gg.y, 0.f);
            As[kv + 2][mm] = fmaxf(v.z + gg.z, 0.f);
            As[kv + 3][mm] = fmaxf(v.w + gg.w, 0.f);
        }
        {
            float4 w = *(const float4*)(wout + (size_t)(n0 + row) * JJ + k0 + kv);
            Bs[kv + 0][row] = w.x;
            Bs[kv + 1][row] = w.y;
            Bs[kv + 2][row] = w.z;
            Bs[kv + 3][row] = w.w;
        }
        __syncthreads();
#pragma unroll
        for (int k = 0; k < 16; k++) {
            float4 a0 = *(float4*)(&As[k][ty * 8]);
            float4 a1 = *(float4*)(&As[k][ty * 8 + 4]);
            float4 bb = *(float4*)(&Bs[k][tx * 4]);
            float a[8] = {a0.x, a0.y, a0.z, a0.w, a1.x, a1.y, a1.z, a1.w};
            float bv[4] = {bb.x, bb.y, bb.z, bb.w};
#pragma unroll
            for (int i = 0; i < 8; i++)
#pragma unroll
                for (int j = 0; j < 4; j++) acc[i][j] = fmaf(a[i], bv[j], acc[i][j]);
        }
        __syncthreads();
    }
    float4 ob = *(const float4*)(outb + n0 + tx * 4);
#pragma unroll
    for (int i = 0; i < 8; i++) {
        long long idx = (long long)(m0 + ty * 8 + i) * VV + n0 + tx * 4;
        if (idx + 3 < out_elems) {
            float4 o;
            o.x = acc[i][0] + ob.x;
            o.y = acc[i][1] + ob.y;
            o.z = acc[i][2] + ob.z;
            o.w = acc[i][3] + ob.w;
            *(float4*)(&out[idx]) = o;
        }
    }
}

// ---------------- tail: target_length + stacked states (bounds-guarded) ----------------
__global__ void tail_k(const int* __restrict__ tlen, float* __restrict__ out,
                       long long out_elems) {
    int i = blockIdx.x * blockDim.x + threadIdx.x;
    long long base = (long long)BB * TT * VV;
    if (i < BB) {
        long long idx = base + i;
        if (idx < out_elems) out[idx] = (float)tlen[i];
    }
    if (i < 2 * BB * HH) {
        float h = (i < BB * HH) ? d_h0[i] : d_h1[i - BB * HH];
        float c = (i < BB * HH) ? d_c0[i] : d_c1[i - BB * HH];
        long long ih = base + BB + i;
        long long ic = base + BB + 2LL * BB * HH + i;
        if (ih < out_elems) out[ih] = h;
        if (ic < out_elems) out[ic] = c;
    }
}

extern "C" void kernel_launch(void* const* d_in, const int* in_sizes, int n_in,
                              void* d_out, int out_size) {
    const float* enc       = (const float*)d_in[0];
    const int* targ        = (const int*)d_in[1];     // int32 (JAX default x64-off)
    const int* tlen        = (const int*)d_in[2];
    const float* st1       = (const float*)d_in[3];   // (2,B,H) h states
    const float* st2       = (const float*)d_in[4];   // (2,B,H) c states
    const float* wih0      = (const float*)d_in[5];
    const float* whh0      = (const float*)d_in[6];
    const float* bih0      = (const float*)d_in[7];
    const float* bhh0      = (const float*)d_in[8];
    const float* wih1      = (const float*)d_in[9];
    const float* whh1      = (const float*)d_in[10];
    const float* bih1      = (const float*)d_in[11];
    const float* bhh1      = (const float*)d_in[12];
    const float* embw      = (const float*)d_in[13];
    const float* wenc      = (const float*)d_in[14];
    const float* encb      = (const float*)d_in[15];
    const float* wpred     = (const float*)d_in[16];
    const float* pbias     = (const float*)d_in[17];
    const float* wout      = (const float*)d_in[18];
    const float* outb      = (const float*)d_in[19];
    float* out = (float*)d_out;
    long long out_elems = (long long)out_size;

    embed_k<<<(BB * EE + 255) / 256, 256>>>(targ, embw);

    gates_k<<<dim3(G4 / 128, BB), 128>>>(0, st1, wih0, whh0, bih0, bhh0);
    lstm_pw_k<<<(BB * HH + 255) / 256, 256>>>(0, st2);

    gates_k<<<dim3(G4 / 128, BB), 128>>>(1, st1 + (size_t)BB * HH, wih1, whh1, bih1, bhh1);
    lstm_pw_k<<<(BB * HH + 255) / 256, 256>>>(1, st2 + (size_t)BB * HH);

    pred_k<<<dim3(JJ / 128, BB), 128>>>(wpred, pbias);

    fgemm_k<<<dim3(BB * TT / 128, JJ / 64), 256>>>(enc, wenc, encb);

    outgemm_k<<<dim3(BB * TT / 128, VV / 64), 256>>>(wout, outb, out, out_elems);

    tail_k<<<(2 * BB * HH + 255) / 256, 256>>>(tlen, out, out_elems);
}

// round 7
// speedup vs baseline: 3.1228x; 3.1228x over previous
#include <cuda_runtime.h>
#include <cuda_fp16.h>
#include <mma.h>
#include <cstdint>

using namespace nvcuda;

#define BB 32
#define TT 512
#define DENC 512
#define HH 640
#define EE 640
#define JJ 640
#define VV 4096
#define G4 2560   // 4*H
#define KSPL 4

// ---------------- scratch (static device allocations, allowed) ----------------
__device__ float d_xt[BB * EE];
__device__ float d_gates_p[KSPL][BB][G4];
__device__ float d_h0[BB * HH];
__device__ float d_c0[BB * HH];
__device__ float d_h1[BB * HH];
__device__ float d_c1[BB * HH];
__device__ float d_gvec_p[2][BB][JJ];
__device__ float d_gvec[BB * JJ];
__device__ __half d_fa[BB * TT * JJ];   // relu(f+g) in fp16, 16384 x 640 (~21 MB)
__device__ __half d_wh[VV * JJ];        // wout in fp16 (~5.2 MB)

__device__ __forceinline__ float sigmoidf(float x) {
    return 1.0f / (1.0f + expf(-x));
}

// ---------------- embedding lookup (targets int32) ----------------
__global__ void embed_k(const int* __restrict__ targets,
                        const float* __restrict__ embw) {
    int i = blockIdx.x * blockDim.x + threadIdx.x;  // B*E
    if (i >= BB * EE) return;
    int b = i / EE, e = i % EE;
    int tok = targets[b];
    if (tok < 0 || tok >= VV) tok = 0;
    d_xt[i] = embw[(size_t)tok * EE + e];
}

// ---------------- LSTM gates (batched weight reuse + k-split) ----------------
__global__ void __launch_bounds__(128) gates2_k(int layer, const float* __restrict__ hprev,
                                                const float* __restrict__ wih,
                                                const float* __restrict__ whh) {
    int tid = threadIdx.x;
    int j = blockIdx.x * 128 + tid;
    int kq = blockIdx.y;                  // 0..3
    int kbeg = kq * 320;                  // in combined 1280 space
    const float* x = (layer == 0) ? d_xt : d_h0;
    const float* src;
    const float* w;
    int off;
    if (kbeg < EE) { src = x; w = wih; off = kbeg; }
    else           { src = hprev; w = whh; off = kbeg - EE; }

    __shared__ float xs[BB][320];
    for (int idx = tid; idx < BB * 80; idx += 128) {   // 80 float4 per row
        int b = idx / 80, c = idx % 80;
        *(float4*)(&xs[b][c * 4]) = *(const float4*)(src + (size_t)b * 640 + off + c * 4);
    }
    __syncthreads();

    float acc[BB];
#pragma unroll
    for (int b = 0; b < BB; b++) acc[b] = 0.f;

    const float4* wr = (const float4*)(w + (size_t)j * 640 + off);
    for (int kc = 0; kc < 80; kc++) {
        float4 wv = wr[kc];
#pragma unroll
        for (int b = 0; b < BB; b++) {
            float4 xv = *(const float4*)(&xs[b][kc * 4]);
            acc[b] = fmaf(wv.x, xv.x, fmaf(wv.y, xv.y, fmaf(wv.z, xv.z, fmaf(wv.w, xv.w, acc[b]))));
        }
    }
#pragma unroll
    for (int b = 0; b < BB; b++) d_gates_p[kq][b][j] = acc[b];
}

// ---------------- LSTM pointwise (sums partials + biases) ----------------
__global__ void lstm_pw_k(int layer, const float* __restrict__ cprev,
                          const float* __restrict__ bih, const float* __restrict__ bhh) {
    int i = blockIdx.x * blockDim.x + threadIdx.x;  // B*H
    if (i >= BB * HH) return;
    int b = i / HH;
    int j = i % HH;
    float gv[4];
#pragma unroll
    for (int gidx = 0; gidx < 4; gidx++) {
        int jj = gidx * HH + j;
        float s = bih[jj] + bhh[jj];
#pragma unroll
        for (int q = 0; q < KSPL; q++) s += d_gates_p[q][b][jj];
        gv[gidx] = s;
    }
    float ig = sigmoidf(gv[0]);
    float fg = sigmoidf(gv[1]);
    float gg = tanhf(gv[2]);
    float og = sigmoidf(gv[3]);
    float c = fg * cprev[i] + ig * gg;
    float h = og * tanhf(c);
    if (layer == 0) { d_c0[i] = c; d_h0[i] = h; }
    else            { d_c1[i] = c; d_h1[i] = h; }
}

// ---------------- pred head (batched weight reuse, k-split 2) ----------------
__global__ void __launch_bounds__(128) pred2_k(const float* __restrict__ wp) {
    int tid = threadIdx.x;
    int j = blockIdx.x * 128 + tid;
    int kq = blockIdx.y;            // 0..1
    int off = kq * 320;

    __shared__ float xs[BB][320];
    for (int idx = tid; idx < BB * 80; idx += 128) {
        int b = idx / 80, c = idx % 80;
        *(float4*)(&xs[b][c * 4]) = *(const float4*)(d_h1 + (size_t)b * HH + off + c * 4);
    }
    __syncthreads();

    float acc[BB];
#pragma unroll
    for (int b = 0; b < BB; b++) acc[b] = 0.f;
    const float4* wr = (const float4*)(wp + (size_t)j * HH + off);
    for (int kc = 0; kc < 80; kc++) {
        float4 wv = wr[kc];
#pragma unroll
        for (int b = 0; b < BB; b++) {
            float4 xv = *(const float4*)(&xs[b][kc * 4]);
            acc[b] = fmaf(wv.x, xv.x, fmaf(wv.y, xv.y, fmaf(wv.z, xv.z, fmaf(wv.w, xv.w, acc[b]))));
        }
    }
#pragma unroll
    for (int b = 0; b < BB; b++) d_gvec_p[kq][b][j] = acc[b];
}

__global__ void gcomb_k(const float* __restrict__ pb) {
    int i = blockIdx.x * blockDim.x + threadIdx.x;   // B*J
    if (i >= BB * JJ) return;
    int b = i / JJ, j = i % JJ;
    d_gvec[i] = d_gvec_p[0][b][j] + d_gvec_p[1][b][j] + pb[j];
}

// ---------------- wout -> fp16 ----------------
__global__ void wconv_k(const float* __restrict__ wout) {
    int i = blockIdx.x * blockDim.x + threadIdx.x;   // over float4 groups
    if (i >= VV * JJ / 4) return;
    float4 v = ((const float4*)wout)[i];
    __half2 h0 = __floats2half2_rn(v.x, v.y);
    __half2 h1 = __floats2half2_rn(v.z, v.w);
    uint2 u;
    u.x = *(uint32_t*)&h0;
    u.y = *(uint32_t*)&h1;
    *(uint2*)(&d_wh[(size_t)i * 4]) = u;
}

// ---------------- f GEMM (fp32 SIMT) + fused relu(f+g) -> fp16 epilogue ----------------
__global__ void __launch_bounds__(256) fgemm_k(const float* __restrict__ enc,
                                               const float* __restrict__ wenc,
                                               const float* __restrict__ encb) {
    __shared__ float As[16][128];
    __shared__ float Bs[16][64];
    int m0 = blockIdx.x * 128;
    int n0 = blockIdx.y * 64;
    int b = m0 / TT;
    int t0 = m0 % TT;
    int tid = threadIdx.x;
    int tx = tid % 16, ty = tid / 16;

    const float* encB = enc + (size_t)b * DENC * TT;
    float acc[8][4];
#pragma unroll
    for (int i = 0; i < 8; i++)
#pragma unroll
        for (int j = 0; j < 4; j++) acc[i][j] = 0.f;

    int kl = tid >> 5;
    int mv = (tid & 31) << 2;
    int nn = tid >> 2;
    int kv = (tid & 3) << 2;

    for (int k0 = 0; k0 < DENC; k0 += 16) {
#pragma unroll
        for (int r = 0; r < 2; r++) {
            int kk = kl + r * 8;
            float4 v = *(const float4*)(encB + (size_t)(k0 + kk) * TT + t0 + mv);
            *(float4*)(&As[kk][mv]) = v;
        }
        {
            float4 w = *(const float4*)(wenc + (size_t)(n0 + nn) * DENC + k0 + kv);
            Bs[kv + 0][nn] = w.x;
            Bs[kv + 1][nn] = w.y;
            Bs[kv + 2][nn] = w.z;
            Bs[kv + 3][nn] = w.w;
        }
        __syncthreads();
#pragma unroll
        for (int k = 0; k < 16; k++) {
            float4 a0 = *(float4*)(&As[k][ty * 8]);
            float4 a1 = *(float4*)(&As[k][ty * 8 + 4]);
            float4 bb = *(float4*)(&Bs[k][tx * 4]);
            float a[8] = {a0.x, a0.y, a0.z, a0.w, a1.x, a1.y, a1.z, a1.w};
            float bv[4] = {bb.x, bb.y, bb.z, bb.w};
#pragma unroll
            for (int i = 0; i < 8; i++)
#pragma unroll
                for (int j = 0; j < 4; j++) acc[i][j] = fmaf(a[i], bv[j], acc[i][j]);
        }
        __syncthreads();
    }
    float4 eb = *(const float4*)(encb + n0 + tx * 4);
    float4 gg = *(const float4*)(d_gvec + (size_t)b * JJ + n0 + tx * 4);
#pragma unroll
    for (int i = 0; i < 8; i++) {
        float v0 = fmaxf(acc[i][0] + eb.x + gg.x, 0.f);
        float v1 = fmaxf(acc[i][1] + eb.y + gg.y, 0.f);
        float v2 = fmaxf(acc[i][2] + eb.z + gg.z, 0.f);
        float v3 = fmaxf(acc[i][3] + eb.w + gg.w, 0.f);
        __half2 h0 = __floats2half2_rn(v0, v1);
        __half2 h1 = __floats2half2_rn(v2, v3);
        uint2 u;
        u.x = *(uint32_t*)&h0;
        u.y = *(uint32_t*)&h1;
        *(uint2*)(&d_fa[(size_t)(m0 + ty * 8 + i) * JJ + n0 + tx * 4]) = u;
    }
}

// ================= wmma fp16 out GEMM =================
// out[m][v] = sum_k a[m][k] * wh[v][k] + ob[v],  a = relu(f+g) fp16 precomputed
// M=16384, N=4096, K=640. Tile 128x128, BK=32, 8 warps (2m x 4n), wmma 16x16x16.
#define OB_BM 128
#define OB_BN 128
#define OB_BK 32
#define OB_LDS 48          // padded k-stride in halves (16B-aligned rows)
#define OB_STAG_LD 132
// dynamic smem: As(128*48*2=12288) + Bs(12288) = 24576 ; staging 64*132*4 = 33792
#define OB_SMEM 34816

__global__ void __launch_bounds__(256) outgemm_w_k(const float* __restrict__ outb,
                                                   float* __restrict__ out,
                                                   long long out_elems) {
    extern __shared__ char dsm[];
    __half* As = (__half*)dsm;
    __half* Bs = (__half*)(dsm + 12288);
    float* stag = (float*)dsm;

    int tid = threadIdx.x;
    int wid = tid >> 5;
    int wm = wid >> 2;       // 0..1
    int wn = wid & 3;        // 0..3
    int m0 = blockIdx.x * OB_BM;
    int n0 = blockIdx.y * OB_BN;

    wmma::fragment<wmma::accumulator, 16, 16, 16, float> acc[4][2];
#pragma unroll
    for (int i = 0; i < 4; i++)
#pragma unroll
        for (int j = 0; j < 2; j++) wmma::fill_fragment(acc[i][j], 0.f);

    for (int k0 = 0; k0 < JJ; k0 += OB_BK) {
        // load A tile (128 rows x 32 k) and B tile; uint4 = 8 halves per load
#pragma unroll
        for (int r = 0; r < 2; r++) {
            int idx = r * 256 + tid;            // 0..511
            int row = idx >> 2;
            int qc = (idx & 3) << 3;            // half offset 0,8,16,24
            *(uint4*)(&As[row * OB_LDS + qc]) =
                *(const uint4*)(&d_fa[(size_t)(m0 + row) * JJ + k0 + qc]);
            *(uint4*)(&Bs[row * OB_LDS + qc]) =
                *(const uint4*)(&d_wh[(size_t)(n0 + row) * JJ + k0 + qc]);
        }
        __syncthreads();

#pragma unroll
        for (int ks = 0; ks < 2; ks++) {
            wmma::fragment<wmma::matrix_a, 16, 16, 16, __half, wmma::row_major> af[4];
            wmma::fragment<wmma::matrix_b, 16, 16, 16, __half, wmma::col_major> bf[2];
#pragma unroll
            for (int i = 0; i < 4; i++)
                wmma::load_matrix_sync(af[i], &As[(wm * 64 + i * 16) * OB_LDS + ks * 16], OB_LDS);
#pragma unroll
            for (int j = 0; j < 2; j++)
                wmma::load_matrix_sync(bf[j], &Bs[(wn * 32 + j * 16) * OB_LDS + ks * 16], OB_LDS);
#pragma unroll
            for (int i = 0; i < 4; i++)
#pragma unroll
                for (int j = 0; j < 2; j++)
                    wmma::mma_sync(acc[i][j], af[i], bf[j], acc[i][j]);
        }
        __syncthreads();
    }

    // epilogue: two passes of 64 rows through fp32 staging
#pragma unroll
    for (int p = 0; p < 2; p++) {
        if (wm == p) {
#pragma unroll
            for (int i = 0; i < 4; i++)
#pragma unroll
                for (int j = 0; j < 2; j++)
                    wmma::store_matrix_sync(&stag[(i * 16) * OB_STAG_LD + wn * 32 + j * 16],
                                            acc[i][j], OB_STAG_LD, wmma::mem_row_major);
        }
        __syncthreads();
        for (int t = tid; t < 64 * 32; t += 256) {     // 32 float4 groups per row
            int rr = t >> 5;
            int c4 = (t & 31) << 2;
            float4 v = *(float4*)(&stag[rr * OB_STAG_LD + c4]);
            float4 bias = *(const float4*)(outb + n0 + c4);
            long long idx = (long long)(m0 + p * 64 + rr) * VV + n0 + c4;
            if (idx + 3 < out_elems) {
                float4 o;
                o.x = v.x + bias.x;
                o.y = v.y + bias.y;
                o.z = v.z + bias.z;
                o.w = v.w + bias.w;
                *(float4*)(&out[idx]) = o;
            }
        }
        __syncthreads();
    }
}

// ---------------- tail ----------------
__global__ void tail_k(const int* __restrict__ tlen, float* __restrict__ out,
                       long long out_elems) {
    int i = blockIdx.x * blockDim.x + threadIdx.x;
    long long base = (long long)BB * TT * VV;
    if (i < BB) {
        long long idx = base + i;
        if (idx < out_elems) out[idx] = (float)tlen[i];
    }
    if (i < 2 * BB * HH) {
        float h = (i < BB * HH) ? d_h0[i] : d_h1[i - BB * HH];
        float c = (i < BB * HH) ? d_c0[i] : d_c1[i - BB * HH];
        long long ih = base + BB + i;
        long long ic = base + BB + 2LL * BB * HH + i;
        if (ih < out_elems) out[ih] = h;
        if (ic < out_elems) out[ic] = c;
    }
}

extern "C" void kernel_launch(void* const* d_in, const int* in_sizes, int n_in,
                              void* d_out, int out_size) {
    const float* enc       = (const float*)d_in[0];
    const int* targ        = (const int*)d_in[1];
    const int* tlen        = (const int*)d_in[2];
    const float* st1       = (const float*)d_in[3];
    const float* st2       = (const float*)d_in[4];
    const float* wih0      = (const float*)d_in[5];
    const float* whh0      = (const float*)d_in[6];
    const float* bih0      = (const float*)d_in[7];
    const float* bhh0      = (const float*)d_in[8];
    const float* wih1      = (const float*)d_in[9];
    const float* whh1      = (const float*)d_in[10];
    const float* bih1      = (const float*)d_in[11];
    const float* bhh1      = (const float*)d_in[12];
    const float* embw      = (const float*)d_in[13];
    const float* wenc      = (const float*)d_in[14];
    const float* encb      = (const float*)d_in[15];
    const float* wpred     = (const float*)d_in[16];
    const float* pbias     = (const float*)d_in[17];
    const float* wout      = (const float*)d_in[18];
    const float* outb      = (const float*)d_in[19];
    float* out = (float*)d_out;
    long long out_elems = (long long)out_size;

    embed_k<<<(BB * EE + 255) / 256, 256>>>(targ, embw);
    wconv_k<<<(VV * JJ / 4 + 255) / 256, 256>>>(wout);

    gates2_k<<<dim3(G4 / 128, KSPL), 128>>>(0, st1, wih0, whh0);
    lstm_pw_k<<<(BB * HH + 255) / 256, 256>>>(0, st2, bih0, bhh0);

    gates2_k<<<dim3(G4 / 128, KSPL), 128>>>(1, st1 + (size_t)BB * HH, wih1, whh1);
    lstm_pw_k<<<(BB * HH + 255) / 256, 256>>>(1, st2 + (size_t)BB * HH, bih1, bhh1);

    pred2_k<<<dim3(JJ / 128, 2), 128>>>(wpred);
    gcomb_k<<<(BB * JJ + 255) / 256, 256>>>(pbias);

    fgemm_k<<<dim3(BB * TT / 128, JJ / 64), 256>>>(enc, wenc, encb);

    outgemm_w_k<<<dim3(BB * TT / OB_BM, VV / OB_BN), 256, OB_SMEM>>>(outb, out, out_elems);

    tail_k<<<(2 * BB * HH + 255) / 256, 256>>>(tlen, out, out_elems);
}

// round 8
// speedup vs baseline: 3.7980x; 1.2162x over previous
#include <cuda_runtime.h>
#include <cuda_fp16.h>
#include <mma.h>
#include <cstdint>

using namespace nvcuda;

#define BB 32
#define TT 512
#define DENC 512
#define HH 640
#define EE 640
#define JJ 640
#define VV 4096
#define G4 2560   // 4*H
#define KSPL 4

// ---------------- scratch (static device allocations, allowed) ----------------
__device__ float d_xt[BB * EE];
__device__ float d_gates_p[KSPL][BB][G4];
__device__ float d_h0[BB * HH];
__device__ float d_c0[BB * HH];
__device__ float d_h1[BB * HH];
__device__ float d_c1[BB * HH];
__device__ float d_gvec_p[2][BB][JJ];
__device__ float d_gvec[BB * JJ];
__device__ __half d_fa[BB * TT * JJ];   // relu(f+g) fp16, 16384 x 640 (~21 MB)
__device__ __half d_wh[VV * JJ];        // wout fp16 (~5.2 MB)
__device__ __half d_ea[BB * TT * DENC]; // enc transposed fp16, 16384 x 512 (~16.8 MB)
__device__ __half d_we[JJ * DENC];      // wenc fp16 (~0.65 MB)

__device__ __forceinline__ float sigmoidf(float x) {
    return 1.0f / (1.0f + expf(-x));
}

// ---------------- embedding lookup (targets int32) ----------------
__global__ void embed_k(const int* __restrict__ targets,
                        const float* __restrict__ embw) {
    int i = blockIdx.x * blockDim.x + threadIdx.x;  // B*E
    if (i >= BB * EE) return;
    int b = i / EE, e = i % EE;
    int tok = targets[b];
    if (tok < 0 || tok >= VV) tok = 0;
    d_xt[i] = embw[(size_t)tok * EE + e];
}

// ---------------- LSTM gates (batched weight reuse + k-split) ----------------
__global__ void __launch_bounds__(128) gates2_k(int layer, const float* __restrict__ hprev,
                                                const float* __restrict__ wih,
                                                const float* __restrict__ whh) {
    int tid = threadIdx.x;
    int j = blockIdx.x * 128 + tid;
    int kq = blockIdx.y;                  // 0..3
    int kbeg = kq * 320;                  // in combined 1280 space
    const float* x = (layer == 0) ? d_xt : d_h0;
    const float* src;
    const float* w;
    int off;
    if (kbeg < EE) { src = x; w = wih; off = kbeg; }
    else           { src = hprev; w = whh; off = kbeg - EE; }

    __shared__ float xs[BB][320];
    for (int idx = tid; idx < BB * 80; idx += 128) {
        int b = idx / 80, c = idx % 80;
        *(float4*)(&xs[b][c * 4]) = *(const float4*)(src + (size_t)b * 640 + off + c * 4);
    }
    __syncthreads();

    float acc[BB];
#pragma unroll
    for (int b = 0; b < BB; b++) acc[b] = 0.f;

    const float4* wr = (const float4*)(w + (size_t)j * 640 + off);
    for (int kc = 0; kc < 80; kc++) {
        float4 wv = wr[kc];
#pragma unroll
        for (int b = 0; b < BB; b++) {
            float4 xv = *(const float4*)(&xs[b][kc * 4]);
            acc[b] = fmaf(wv.x, xv.x, fmaf(wv.y, xv.y, fmaf(wv.z, xv.z, fmaf(wv.w, xv.w, acc[b]))));
        }
    }
#pragma unroll
    for (int b = 0; b < BB; b++) d_gates_p[kq][b][j] = acc[b];
}

// ---------------- LSTM pointwise ----------------
__global__ void lstm_pw_k(int layer, const float* __restrict__ cprev,
                          const float* __restrict__ bih, const float* __restrict__ bhh) {
    int i = blockIdx.x * blockDim.x + threadIdx.x;  // B*H
    if (i >= BB * HH) return;
    int b = i / HH;
    int j = i % HH;
    float gv[4];
#pragma unroll
    for (int gidx = 0; gidx < 4; gidx++) {
        int jj = gidx * HH + j;
        float s = bih[jj] + bhh[jj];
#pragma unroll
        for (int q = 0; q < KSPL; q++) s += d_gates_p[q][b][jj];
        gv[gidx] = s;
    }
    float ig = sigmoidf(gv[0]);
    float fg = sigmoidf(gv[1]);
    float gg = tanhf(gv[2]);
    float og = sigmoidf(gv[3]);
    float c = fg * cprev[i] + ig * gg;
    float h = og * tanhf(c);
    if (layer == 0) { d_c0[i] = c; d_h0[i] = h; }
    else            { d_c1[i] = c; d_h1[i] = h; }
}

// ---------------- pred head ----------------
__global__ void __launch_bounds__(128) pred2_k(const float* __restrict__ wp) {
    int tid = threadIdx.x;
    int j = blockIdx.x * 128 + tid;
    int kq = blockIdx.y;
    int off = kq * 320;

    __shared__ float xs[BB][320];
    for (int idx = tid; idx < BB * 80; idx += 128) {
        int b = idx / 80, c = idx % 80;
        *(float4*)(&xs[b][c * 4]) = *(const float4*)(d_h1 + (size_t)b * HH + off + c * 4);
    }
    __syncthreads();

    float acc[BB];
#pragma unroll
    for (int b = 0; b < BB; b++) acc[b] = 0.f;
    const float4* wr = (const float4*)(wp + (size_t)j * HH + off);
    for (int kc = 0; kc < 80; kc++) {
        float4 wv = wr[kc];
#pragma unroll
        for (int b = 0; b < BB; b++) {
            float4 xv = *(const float4*)(&xs[b][kc * 4]);
            acc[b] = fmaf(wv.x, xv.x, fmaf(wv.y, xv.y, fmaf(wv.z, xv.z, fmaf(wv.w, xv.w, acc[b]))));
        }
    }
#pragma unroll
    for (int b = 0; b < BB; b++) d_gvec_p[kq][b][j] = acc[b];
}

__global__ void gcomb_k(const float* __restrict__ pb) {
    int i = blockIdx.x * blockDim.x + threadIdx.x;   // B*J
    if (i >= BB * JJ) return;
    int b = i / JJ, j = i % JJ;
    d_gvec[i] = d_gvec_p[0][b][j] + d_gvec_p[1][b][j] + pb[j];
}

// ---------------- generic fp32 -> fp16 convert (float4 granularity) ----------------
__global__ void hconv_k(const float* __restrict__ src, __half* __restrict__ dst, int n4) {
    int i = blockIdx.x * blockDim.x + threadIdx.x;
    if (i >= n4) return;
    float4 v = ((const float4*)src)[i];
    __half2 h0 = __floats2half2_rn(v.x, v.y);
    __half2 h1 = __floats2half2_rn(v.z, v.w);
    uint2 u;
    u.x = *(uint32_t*)&h0;
    u.y = *(uint32_t*)&h1;
    *(uint2*)(&dst[(size_t)i * 4]) = u;
}

// ---------------- enc transpose-convert: (B, K=512, T=512) f32 -> d_ea[b*T+t][k] f16 ----
__global__ void __launch_bounds__(256) econv_k(const float* __restrict__ enc) {
    __shared__ float tile[32][33];
    int b = blockIdx.z;
    int k0 = blockIdx.y * 32;
    int t0 = blockIdx.x * 32;
    int tx = threadIdx.x & 31;
    int ty = threadIdx.x >> 5;    // 0..7
    const float* e = enc + (size_t)b * DENC * TT;
#pragma unroll
    for (int r = 0; r < 4; r++) {
        int kk = ty + r * 8;
        tile[kk][tx] = e[(size_t)(k0 + kk) * TT + t0 + tx];
    }
    __syncthreads();
#pragma unroll
    for (int r = 0; r < 4; r++) {
        int tt = ty + r * 8;
        d_ea[(size_t)(b * TT + t0 + tt) * DENC + k0 + tx] =
            __float2half_rn(tile[tx][tt]);
    }
}

// ================= wmma fp16 f GEMM =================
// f[m][n] = relu(sum_k ea[m][k]*we[n][k] + encb[n] + gvec[b][n]) -> d_fa fp16
// M=16384, N=640, K=512. Tile 128x128, BK=32, 8 warps (2m x 4n).
#define OB_LDS 48
#define OB_STAG_LD 132
#define OB_SMEM 34816

__global__ void __launch_bounds__(256) fgemm_w_k(const float* __restrict__ encb) {
    extern __shared__ char dsm[];
    __half* As = (__half*)dsm;
    __half* Bs = (__half*)(dsm + 12288);
    float* stag = (float*)dsm;

    int tid = threadIdx.x;
    int wid = tid >> 5;
    int wm = wid >> 2;
    int wn = wid & 3;
    int m0 = blockIdx.x * 128;
    int n0 = blockIdx.y * 128;
    int b = m0 / TT;

    wmma::fragment<wmma::accumulator, 16, 16, 16, float> acc[4][2];
#pragma unroll
    for (int i = 0; i < 4; i++)
#pragma unroll
        for (int j = 0; j < 2; j++) wmma::fill_fragment(acc[i][j], 0.f);

    for (int k0 = 0; k0 < DENC; k0 += 32) {
#pragma unroll
        for (int r = 0; r < 2; r++) {
            int idx = r * 256 + tid;
            int row = idx >> 2;
            int qc = (idx & 3) << 3;
            *(uint4*)(&As[row * OB_LDS + qc]) =
                *(const uint4*)(&d_ea[(size_t)(m0 + row) * DENC + k0 + qc]);
            *(uint4*)(&Bs[row * OB_LDS + qc]) =
                *(const uint4*)(&d_we[(size_t)(n0 + row) * DENC + k0 + qc]);
        }
        __syncthreads();
#pragma unroll
        for (int ks = 0; ks < 2; ks++) {
            wmma::fragment<wmma::matrix_a, 16, 16, 16, __half, wmma::row_major> af[4];
            wmma::fragment<wmma::matrix_b, 16, 16, 16, __half, wmma::col_major> bf[2];
#pragma unroll
            for (int i = 0; i < 4; i++)
                wmma::load_matrix_sync(af[i], &As[(wm * 64 + i * 16) * OB_LDS + ks * 16], OB_LDS);
#pragma unroll
            for (int j = 0; j < 2; j++)
                wmma::load_matrix_sync(bf[j], &Bs[(wn * 32 + j * 16) * OB_LDS + ks * 16], OB_LDS);
#pragma unroll
            for (int i = 0; i < 4; i++)
#pragma unroll
                for (int j = 0; j < 2; j++)
                    wmma::mma_sync(acc[i][j], af[i], bf[j], acc[i][j]);
        }
        __syncthreads();
    }

#pragma unroll
    for (int p = 0; p < 2; p++) {
        if (wm == p) {
#pragma unroll
            for (int i = 0; i < 4; i++)
#pragma unroll
                for (int j = 0; j < 2; j++)
                    wmma::store_matrix_sync(&stag[(i * 16) * OB_STAG_LD + wn * 32 + j * 16],
                                            acc[i][j], OB_STAG_LD, wmma::mem_row_major);
        }
        __syncthreads();
        for (int t = tid; t < 64 * 32; t += 256) {
            int rr = t >> 5;
            int c4 = (t & 31) << 2;
            float4 v = *(float4*)(&stag[rr * OB_STAG_LD + c4]);
            float4 eb = *(const float4*)(encb + n0 + c4);
            float4 gg = *(const float4*)(d_gvec + (size_t)b * JJ + n0 + c4);
            float v0 = fmaxf(v.x + eb.x + gg.x, 0.f);
            float v1 = fmaxf(v.y + eb.y + gg.y, 0.f);
            float v2 = fmaxf(v.z + eb.z + gg.z, 0.f);
            float v3 = fmaxf(v.w + eb.w + gg.w, 0.f);
            __half2 h0 = __floats2half2_rn(v0, v1);
            __half2 h1 = __floats2half2_rn(v2, v3);
            uint2 u;
            u.x = *(uint32_t*)&h0;
            u.y = *(uint32_t*)&h1;
            *(uint2*)(&d_fa[(size_t)(m0 + p * 64 + rr) * JJ + n0 + c4]) = u;
        }
        __syncthreads();
    }
}

// ================= wmma fp16 out GEMM =================
__global__ void __launch_bounds__(256) outgemm_w_k(const float* __restrict__ outb,
                                                   float* __restrict__ out,
                                                   long long out_elems) {
    extern __shared__ char dsm[];
    __half* As = (__half*)dsm;
    __half* Bs = (__half*)(dsm + 12288);
    float* stag = (float*)dsm;

    int tid = threadIdx.x;
    int wid = tid >> 5;
    int wm = wid >> 2;
    int wn = wid & 3;
    int m0 = blockIdx.x * 128;
    int n0 = blockIdx.y * 128;

    wmma::fragment<wmma::accumulator, 16, 16, 16, float> acc[4][2];
#pragma unroll
    for (int i = 0; i < 4; i++)
#pragma unroll
        for (int j = 0; j < 2; j++) wmma::fill_fragment(acc[i][j], 0.f);

    for (int k0 = 0; k0 < JJ; k0 += 32) {
#pragma unroll
        for (int r = 0; r < 2; r++) {
            int idx = r * 256 + tid;
            int row = idx >> 2;
            int qc = (idx & 3) << 3;
            *(uint4*)(&As[row * OB_LDS + qc]) =
                *(const uint4*)(&d_fa[(size_t)(m0 + row) * JJ + k0 + qc]);
            *(uint4*)(&Bs[row * OB_LDS + qc]) =
                *(const uint4*)(&d_wh[(size_t)(n0 + row) * JJ + k0 + qc]);
        }
        __syncthreads();
#pragma unroll
        for (int ks = 0; ks < 2; ks++) {
            wmma::fragment<wmma::matrix_a, 16, 16, 16, __half, wmma::row_major> af[4];
            wmma::fragment<wmma::matrix_b, 16, 16, 16, __half, wmma::col_major> bf[2];
#pragma unroll
            for (int i = 0; i < 4; i++)
                wmma::load_matrix_sync(af[i], &As[(wm * 64 + i * 16) * OB_LDS + ks * 16], OB_LDS);
#pragma unroll
            for (int j = 0; j < 2; j++)
                wmma::load_matrix_sync(bf[j], &Bs[(wn * 32 + j * 16) * OB_LDS + ks * 16], OB_LDS);
#pragma unroll
            for (int i = 0; i < 4; i++)
#pragma unroll
                for (int j = 0; j < 2; j++)
                    wmma::mma_sync(acc[i][j], af[i], bf[j], acc[i][j]);
        }
        __syncthreads();
    }

#pragma unroll
    for (int p = 0; p < 2; p++) {
        if (wm == p) {
#pragma unroll
            for (int i = 0; i < 4; i++)
#pragma unroll
                for (int j = 0; j < 2; j++)
                    wmma::store_matrix_sync(&stag[(i * 16) * OB_STAG_LD + wn * 32 + j * 16],
                                            acc[i][j], OB_STAG_LD, wmma::mem_row_major);
        }
        __syncthreads();
        for (int t = tid; t < 64 * 32; t += 256) {
            int rr = t >> 5;
            int c4 = (t & 31) << 2;
            float4 v = *(float4*)(&stag[rr * OB_STAG_LD + c4]);
            float4 bias = *(const float4*)(outb + n0 + c4);
            long long idx = (long long)(m0 + p * 64 + rr) * VV + n0 + c4;
            if (idx + 3 < out_elems) {
                float4 o;
                o.x = v.x + bias.x;
                o.y = v.y + bias.y;
                o.z = v.z + bias.z;
                o.w = v.w + bias.w;
                *(float4*)(&out[idx]) = o;
            }
        }
        __syncthreads();
    }
}

// ---------------- tail ----------------
__global__ void tail_k(const int* __restrict__ tlen, float* __restrict__ out,
                       long long out_elems) {
    int i = blockIdx.x * blockDim.x + threadIdx.x;
    long long base = (long long)BB * TT * VV;
    if (i < BB) {
        long long idx = base + i;
        if (idx < out_elems) out[idx] = (float)tlen[i];
    }
    if (i < 2 * BB * HH) {
        float h = (i < BB * HH) ? d_h0[i] : d_h1[i - BB * HH];
        float c = (i < BB * HH) ? d_c0[i] : d_c1[i - BB * HH];
        long long ih = base + BB + i;
        long long ic = base + BB + 2LL * BB * HH + i;
        if (ih < out_elems) out[ih] = h;
        if (ic < out_elems) out[ic] = c;
    }
}

extern "C" void kernel_launch(void* const* d_in, const int* in_sizes, int n_in,
                              void* d_out, int out_size) {
    const float* enc       = (const float*)d_in[0];
    const int* targ        = (const int*)d_in[1];
    const int* tlen        = (const int*)d_in[2];
    const float* st1       = (const float*)d_in[3];
    const float* st2       = (const float*)d_in[4];
    const float* wih0      = (const float*)d_in[5];
    const float* whh0      = (const float*)d_in[6];
    const float* bih0      = (const float*)d_in[7];
    const float* bhh0      = (const float*)d_in[8];
    const float* wih1      = (const float*)d_in[9];
    const float* whh1      = (const float*)d_in[10];
    const float* bih1      = (const float*)d_in[11];
    const float* bhh1      = (const float*)d_in[12];
    const float* embw      = (const float*)d_in[13];
    const float* wenc      = (const float*)d_in[14];
    const float* encb      = (const float*)d_in[15];
    const float* wpred     = (const float*)d_in[16];
    const float* pbias     = (const float*)d_in[17];
    const float* wout      = (const float*)d_in[18];
    const float* outb      = (const float*)d_in[19];
    float* out = (float*)d_out;
    long long out_elems = (long long)out_size;

    __half *p_wh, *p_we;
    cudaGetSymbolAddress((void**)&p_wh, d_wh);
    cudaGetSymbolAddress((void**)&p_we, d_we);

    embed_k<<<(BB * EE + 255) / 256, 256>>>(targ, embw);
    hconv_k<<<(VV * JJ / 4 + 255) / 256, 256>>>(wout, p_wh, VV * JJ / 4);
    hconv_k<<<(JJ * DENC / 4 + 255) / 256, 256>>>(wenc, p_we, JJ * DENC / 4);
    econv_k<<<dim3(TT / 32, DENC / 32, BB), 256>>>(enc);

    gates2_k<<<dim3(G4 / 128, KSPL), 128>>>(0, st1, wih0, whh0);
    lstm_pw_k<<<(BB * HH + 255) / 256, 256>>>(0, st2, bih0, bhh0);

    gates2_k<<<dim3(G4 / 128, KSPL), 128>>>(1, st1 + (size_t)BB * HH, wih1, whh1);
    lstm_pw_k<<<(BB * HH + 255) / 256, 256>>>(1, st2 + (size_t)BB * HH, bih1, bhh1);

    pred2_k<<<dim3(JJ / 128, 2), 128>>>(wpred);
    gcomb_k<<<(BB * JJ + 255) / 256, 256>>>(pbias);

    fgemm_w_k<<<dim3(BB * TT / 128, JJ / 128), 256, OB_SMEM>>>(encb);

    outgemm_w_k<<<dim3(BB * TT / 128, VV / 128), 256, OB_SMEM>>>(outb, out, out_elems);

    tail_k<<<(2 * BB * HH + 255) / 256, 256>>>(tlen, out, out_elems);
}

// round 9
// speedup vs baseline: 5.4639x; 1.4386x over previous
#include <cuda_runtime.h>
#include <cuda_fp16.h>
#include <mma.h>
#include <cstdint>

using namespace nvcuda;

#define BB 32
#define TT 512
#define DENC 512
#define HH 640
#define EE 640
#define JJ 640
#define VV 4096
#define G4 2560   // 4*H
#define KSPL 4

// ---------------- scratch (static device allocations, allowed) ----------------
__device__ float d_xt[BB * EE];
__device__ float d_gates_p[KSPL][BB][G4];
__device__ float d_h0[BB * HH];
__device__ float d_c0[BB * HH];
__device__ float d_h1[BB * HH];
__device__ float d_c1[BB * HH];
__device__ float d_gvec_p[2][BB][JJ];
__device__ __half d_fa[BB * TT * JJ];   // relu(f+g) fp16, 16384 x 640 (~21 MB)
__device__ __half d_wh[VV * JJ];        // wout fp16 (~5.2 MB)
__device__ __half d_ea[BB * TT * DENC]; // enc transposed fp16, 16384 x 512 (~16.8 MB)
__device__ __half d_we[JJ * DENC];      // wenc fp16 (~0.65 MB)

__device__ __forceinline__ float sigmoidf(float x) {
    return 1.0f / (1.0f + expf(-x));
}

// ---------------- cp.async helpers ----------------
__device__ __forceinline__ void cp16(uint32_t sdst, const void* gsrc) {
    asm volatile("cp.async.cg.shared.global [%0], [%1], 16;" :: "r"(sdst), "l"(gsrc));
}
__device__ __forceinline__ void cp_commit() {
    asm volatile("cp.async.commit_group;" ::: "memory");
}
__device__ __forceinline__ void cp_wait0() {
    asm volatile("cp.async.wait_group 0;" ::: "memory");
}

// ---------------- embedding lookup (targets int32) ----------------
__global__ void embed_k(const int* __restrict__ targets,
                        const float* __restrict__ embw) {
    int i = blockIdx.x * blockDim.x + threadIdx.x;  // B*E
    if (i >= BB * EE) return;
    int b = i / EE, e = i % EE;
    int tok = targets[b];
    if (tok < 0 || tok >= VV) tok = 0;
    d_xt[i] = embw[(size_t)tok * EE + e];
}

// ---------------- LSTM gates (batched weight reuse + k-split) ----------------
__global__ void __launch_bounds__(128) gates2_k(int layer, const float* __restrict__ hprev,
                                                const float* __restrict__ wih,
                                                const float* __restrict__ whh) {
    int tid = threadIdx.x;
    int j = blockIdx.x * 128 + tid;
    int kq = blockIdx.y;                  // 0..3
    int kbeg = kq * 320;                  // in combined 1280 space
    const float* x = (layer == 0) ? d_xt : d_h0;
    const float* src;
    const float* w;
    int off;
    if (kbeg < EE) { src = x; w = wih; off = kbeg; }
    else           { src = hprev; w = whh; off = kbeg - EE; }

    __shared__ float xs[BB][320];
    for (int idx = tid; idx < BB * 80; idx += 128) {
        int b = idx / 80, c = idx % 80;
        *(float4*)(&xs[b][c * 4]) = *(const float4*)(src + (size_t)b * 640 + off + c * 4);
    }
    __syncthreads();

    float acc[BB];
#pragma unroll
    for (int b = 0; b < BB; b++) acc[b] = 0.f;

    const float4* wr = (const float4*)(w + (size_t)j * 640 + off);
    for (int kc = 0; kc < 80; kc++) {
        float4 wv = wr[kc];
#pragma unroll
        for (int b = 0; b < BB; b++) {
            float4 xv = *(const float4*)(&xs[b][kc * 4]);
            acc[b] = fmaf(wv.x, xv.x, fmaf(wv.y, xv.y, fmaf(wv.z, xv.z, fmaf(wv.w, xv.w, acc[b]))));
        }
    }
#pragma unroll
    for (int b = 0; b < BB; b++) d_gates_p[kq][b][j] = acc[b];
}

// ---------------- LSTM pointwise ----------------
__global__ void lstm_pw_k(int layer, const float* __restrict__ cprev,
                          const float* __restrict__ bih, const float* __restrict__ bhh) {
    int i = blockIdx.x * blockDim.x + threadIdx.x;  // B*H
    if (i >= BB * HH) return;
    int b = i / HH;
    int j = i % HH;
    float gv[4];
#pragma unroll
    for (int gidx = 0; gidx < 4; gidx++) {
        int jj = gidx * HH + j;
        float s = bih[jj] + bhh[jj];
#pragma unroll
        for (int q = 0; q < KSPL; q++) s += d_gates_p[q][b][jj];
        gv[gidx] = s;
    }
    float ig = sigmoidf(gv[0]);
    float fg = sigmoidf(gv[1]);
    float gg = tanhf(gv[2]);
    float og = sigmoidf(gv[3]);
    float c = fg * cprev[i] + ig * gg;
    float h = og * tanhf(c);
    if (layer == 0) { d_c0[i] = c; d_h0[i] = h; }
    else            { d_c1[i] = c; d_h1[i] = h; }
}

// ---------------- pred head ----------------
__global__ void __launch_bounds__(128) pred2_k(const float* __restrict__ wp) {
    int tid = threadIdx.x;
    int j = blockIdx.x * 128 + tid;
    int kq = blockIdx.y;
    int off = kq * 320;

    __shared__ float xs[BB][320];
    for (int idx = tid; idx < BB * 80; idx += 128) {
        int b = idx / 80, c = idx % 80;
        *(float4*)(&xs[b][c * 4]) = *(const float4*)(d_h1 + (size_t)b * HH + off + c * 4);
    }
    __syncthreads();

    float acc[BB];
#pragma unroll
    for (int b = 0; b < BB; b++) acc[b] = 0.f;
    const float4* wr = (const float4*)(wp + (size_t)j * HH + off);
    for (int kc = 0; kc < 80; kc++) {
        float4 wv = wr[kc];
#pragma unroll
        for (int b = 0; b < BB; b++) {
            float4 xv = *(const float4*)(&xs[b][kc * 4]);
            acc[b] = fmaf(wv.x, xv.x, fmaf(wv.y, xv.y, fmaf(wv.z, xv.z, fmaf(wv.w, xv.w, acc[b]))));
        }
    }
#pragma unroll
    for (int b = 0; b < BB; b++) d_gvec_p[kq][b][j] = acc[b];
}

// ---------------- generic fp32 -> fp16 convert ----------------
__global__ void hconv_k(const float* __restrict__ src, __half* __restrict__ dst, int n4) {
    int i = blockIdx.x * blockDim.x + threadIdx.x;
    if (i >= n4) return;
    float4 v = ((const float4*)src)[i];
    __half2 h0 = __floats2half2_rn(v.x, v.y);
    __half2 h1 = __floats2half2_rn(v.z, v.w);
    uint2 u;
    u.x = *(uint32_t*)&h0;
    u.y = *(uint32_t*)&h1;
    *(uint2*)(&dst[(size_t)i * 4]) = u;
}

// ---------------- enc transpose-convert ----------------
__global__ void __launch_bounds__(256) econv_k(const float* __restrict__ enc) {
    __shared__ float tile[32][33];
    int b = blockIdx.z;
    int k0 = blockIdx.y * 32;
    int t0 = blockIdx.x * 32;
    int tx = threadIdx.x & 31;
    int ty = threadIdx.x >> 5;    // 0..7
    const float* e = enc + (size_t)b * DENC * TT;
#pragma unroll
    for (int r = 0; r < 4; r++) {
        int kk = ty + r * 8;
        tile[kk][tx] = e[(size_t)(k0 + kk) * TT + t0 + tx];
    }
    __syncthreads();
#pragma unroll
    for (int r = 0; r < 4; r++) {
        int tt = ty + r * 8;
        d_ea[(size_t)(b * TT + t0 + tt) * DENC + k0 + tx] =
            __float2half_rn(tile[tx][tt]);
    }
}

// ================= pipelined wmma GEMM common =================
// Tile 128x128, BK=64, 2-stage cp.async double buffer, 8 warps (2m x 4n).
#define P_LDS 72                        // padded halves per row
#define P_STAGE (128 * P_LDS * 2)       // 18432 bytes per matrix per stage
#define P_SMEM (4 * P_STAGE)            // A0 B0 A1 B1 = 73728
#define OB_STAG_LD 132

// load one stage: A rows from ga (k-stride lda), B rows from gb (k-stride ldb)
__device__ __forceinline__ void stage_load(uint32_t sbase, int stage,
                                           const __half* ga, size_t lda, int m0,
                                           const __half* gb, size_t ldb, int n0,
                                           int k0, int tid) {
    uint32_t abase = sbase + stage * 2 * P_STAGE;            // A then B within stage
    uint32_t bbase = abase + P_STAGE;
#pragma unroll
    for (int i = 0; i < 4; i++) {
        int e = i * 256 + tid;            // 0..1023
        int row = e >> 3;
        int q = (e & 7) << 3;             // halves 0,8,...,56
        cp16(abase + (row * P_LDS + q) * 2, ga + (size_t)(m0 + row) * lda + k0 + q);
        cp16(bbase + (row * P_LDS + q) * 2, gb + (size_t)(n0 + row) * ldb + k0 + q);
    }
}

__device__ __forceinline__ void stage_mma(const __half* smem_gen, int stage,
                                          wmma::fragment<wmma::accumulator, 16, 16, 16, float> (&acc)[4][2],
                                          int wm, int wn) {
    const __half* As = smem_gen + stage * 2 * (128 * P_LDS);
    const __half* Bs = As + 128 * P_LDS;
#pragma unroll
    for (int ks = 0; ks < 4; ks++) {
        wmma::fragment<wmma::matrix_a, 16, 16, 16, __half, wmma::row_major> af[4];
        wmma::fragment<wmma::matrix_b, 16, 16, 16, __half, wmma::col_major> bf[2];
#pragma unroll
        for (int i = 0; i < 4; i++)
            wmma::load_matrix_sync(af[i], &As[(wm * 64 + i * 16) * P_LDS + ks * 16], P_LDS);
#pragma unroll
        for (int j = 0; j < 2; j++)
            wmma::load_matrix_sync(bf[j], &Bs[(wn * 32 + j * 16) * P_LDS + ks * 16], P_LDS);
#pragma unroll
        for (int i = 0; i < 4; i++)
#pragma unroll
            for (int j = 0; j < 2; j++)
                wmma::mma_sync(acc[i][j], af[i], bf[j], acc[i][j]);
    }
}

// ================= fgemm (wmma, pipelined): writes relu(f + encb + g) fp16 ==========
__global__ void __launch_bounds__(256) fgemm_w_k(const float* __restrict__ encb,
                                                 const float* __restrict__ pbias) {
    extern __shared__ char dsm[];
    __half* sh = (__half*)dsm;
    float* stag = (float*)dsm;
    uint32_t sbase = (uint32_t)__cvta_generic_to_shared(dsm);

    int tid = threadIdx.x;
    int wid = tid >> 5;
    int wm = wid >> 2;
    int wn = wid & 3;
    int m0 = blockIdx.x * 128;
    int n0 = blockIdx.y * 128;
    int b = m0 / TT;

    wmma::fragment<wmma::accumulator, 16, 16, 16, float> acc[4][2];
#pragma unroll
    for (int i = 0; i < 4; i++)
#pragma unroll
        for (int j = 0; j < 2; j++) wmma::fill_fragment(acc[i][j], 0.f);

    const int NC = DENC / 64;   // 8
    stage_load(sbase, 0, d_ea, DENC, m0, d_we, DENC, n0, 0, tid);
    cp_commit();
    for (int c = 0; c < NC; c++) {
        cp_wait0();
        __syncthreads();
        if (c + 1 < NC) {
            stage_load(sbase, (c + 1) & 1, d_ea, DENC, m0, d_we, DENC, n0, (c + 1) * 64, tid);
            cp_commit();
        }
        stage_mma(sh, c & 1, acc, wm, wn);
        __syncthreads();
    }

    // epilogue: add encb + (gvec_p0+gvec_p1+pbias), relu, -> fp16 d_fa
#pragma unroll
    for (int p = 0; p < 2; p++) {
        if (wm == p) {
#pragma unroll
            for (int i = 0; i < 4; i++)
#pragma unroll
                for (int j = 0; j < 2; j++)
                    wmma::store_matrix_sync(&stag[(i * 16) * OB_STAG_LD + wn * 32 + j * 16],
                                            acc[i][j], OB_STAG_LD, wmma::mem_row_major);
        }
        __syncthreads();
        for (int t = tid; t < 64 * 32; t += 256) {
            int rr = t >> 5;
            int c4 = (t & 31) << 2;
            float4 v = *(float4*)(&stag[rr * OB_STAG_LD + c4]);
            float4 eb = *(const float4*)(encb + n0 + c4);
            float4 g0 = *(const float4*)(&d_gvec_p[0][b][n0 + c4]);
            float4 g1 = *(const float4*)(&d_gvec_p[1][b][n0 + c4]);
            float4 pb = *(const float4*)(pbias + n0 + c4);
            float v0 = fmaxf(v.x + eb.x + g0.x + g1.x + pb.x, 0.f);
            float v1 = fmaxf(v.y + eb.y + g0.y + g1.y + pb.y, 0.f);
            float v2 = fmaxf(v.z + eb.z + g0.z + g1.z + pb.z, 0.f);
            float v3 = fmaxf(v.w + eb.w + g0.w + g1.w + pb.w, 0.f);
            __half2 h0 = __floats2half2_rn(v0, v1);
            __half2 h1 = __floats2half2_rn(v2, v3);
            uint2 u;
            u.x = *(uint32_t*)&h0;
            u.y = *(uint32_t*)&h1;
            *(uint2*)(&d_fa[(size_t)(m0 + p * 64 + rr) * JJ + n0 + c4]) = u;
        }
        __syncthreads();
    }
}

// ================= out GEMM (wmma, pipelined) =================
__global__ void __launch_bounds__(256) outgemm_w_k(const float* __restrict__ outb,
                                                   float* __restrict__ out,
                                                   long long out_elems) {
    extern __shared__ char dsm[];
    __half* sh = (__half*)dsm;
    float* stag = (float*)dsm;
    uint32_t sbase = (uint32_t)__cvta_generic_to_shared(dsm);

    int tid = threadIdx.x;
    int wid = tid >> 5;
    int wm = wid >> 2;
    int wn = wid & 3;
    int m0 = blockIdx.x * 128;
    int n0 = blockIdx.y * 128;

    wmma::fragment<wmma::accumulator, 16, 16, 16, float> acc[4][2];
#pragma unroll
    for (int i = 0; i < 4; i++)
#pragma unroll
        for (int j = 0; j < 2; j++) wmma::fill_fragment(acc[i][j], 0.f);

    const int NC = JJ / 64;   // 10
    stage_load(sbase, 0, d_fa, JJ, m0, d_wh, JJ, n0, 0, tid);
    cp_commit();
    for (int c = 0; c < NC; c++) {
        cp_wait0();
        __syncthreads();
        if (c + 1 < NC) {
            stage_load(sbase, (c + 1) & 1, d_fa, JJ, m0, d_wh, JJ, n0, (c + 1) * 64, tid);
            cp_commit();
        }
        stage_mma(sh, c & 1, acc, wm, wn);
        __syncthreads();
    }

#pragma unroll
    for (int p = 0; p < 2; p++) {
        if (wm == p) {
#pragma unroll
            for (int i = 0; i < 4; i++)
#pragma unroll
                for (int j = 0; j < 2; j++)
                    wmma::store_matrix_sync(&stag[(i * 16) * OB_STAG_LD + wn * 32 + j * 16],
                                            acc[i][j], OB_STAG_LD, wmma::mem_row_major);
        }
        __syncthreads();
        for (int t = tid; t < 64 * 32; t += 256) {
            int rr = t >> 5;
            int c4 = (t & 31) << 2;
            float4 v = *(float4*)(&stag[rr * OB_STAG_LD + c4]);
            float4 bias = *(const float4*)(outb + n0 + c4);
            long long idx = (long long)(m0 + p * 64 + rr) * VV + n0 + c4;
            if (idx + 3 < out_elems) {
                float4 o;
                o.x = v.x + bias.x;
                o.y = v.y + bias.y;
                o.z = v.z + bias.z;
                o.w = v.w + bias.w;
                *(float4*)(&out[idx]) = o;
            }
        }
        __syncthreads();
    }
}

// ---------------- tail ----------------
__global__ void tail_k(const int* __restrict__ tlen, float* __restrict__ out,
                       long long out_elems) {
    int i = blockIdx.x * blockDim.x + threadIdx.x;
    long long base = (long long)BB * TT * VV;
    if (i < BB) {
        long long idx = base + i;
        if (idx < out_elems) out[idx] = (float)tlen[i];
    }
    if (i < 2 * BB * HH) {
        float h = (i < BB * HH) ? d_h0[i] : d_h1[i - BB * HH];
        float c = (i < BB * HH) ? d_c0[i] : d_c1[i - BB * HH];
        long long ih = base + BB + i;
        long long ic = base + BB + 2LL * BB * HH + i;
        if (ih < out_elems) out[ih] = h;
        if (ic < out_elems) out[ic] = c;
    }
}

extern "C" void kernel_launch(void* const* d_in, const int* in_sizes, int n_in,
                              void* d_out, int out_size) {
    const float* enc       = (const float*)d_in[0];
    const int* targ        = (const int*)d_in[1];
    const int* tlen        = (const int*)d_in[2];
    const float* st1       = (const float*)d_in[3];
    const float* st2       = (const float*)d_in[4];
    const float* wih0      = (const float*)d_in[5];
    const float* whh0      = (const float*)d_in[6];
    const float* bih0      = (const float*)d_in[7];
    const float* bhh0      = (const float*)d_in[8];
    const float* wih1      = (const float*)d_in[9];
    const float* whh1      = (const float*)d_in[10];
    const float* bih1      = (const float*)d_in[11];
    const float* bhh1      = (const float*)d_in[12];
    const float* embw      = (const float*)d_in[13];
    const float* wenc      = (const float*)d_in[14];
    const float* encb      = (const float*)d_in[15];
    const float* wpred     = (const float*)d_in[16];
    const float* pbias     = (const float*)d_in[17];
    const float* wout      = (const float*)d_in[18];
    const float* outb      = (const float*)d_in[19];
    float* out = (float*)d_out;
    long long out_elems = (long long)out_size;

    __half *p_wh, *p_we;
    cudaGetSymbolAddress((void**)&p_wh, d_wh);
    cudaGetSymbolAddress((void**)&p_we, d_we);

    cudaFuncSetAttribute(fgemm_w_k, cudaFuncAttributeMaxDynamicSharedMemorySize, P_SMEM);
    cudaFuncSetAttribute(outgemm_w_k, cudaFuncAttributeMaxDynamicSharedMemorySize, P_SMEM);

    embed_k<<<(BB * EE + 255) / 256, 256>>>(targ, embw);
    hconv_k<<<(VV * JJ / 4 + 255) / 256, 256>>>(wout, p_wh, VV * JJ / 4);
    hconv_k<<<(JJ * DENC / 4 + 255) / 256, 256>>>(wenc, p_we, JJ * DENC / 4);
    econv_k<<<dim3(TT / 32, DENC / 32, BB), 256>>>(enc);

    gates2_k<<<dim3(G4 / 128, KSPL), 128>>>(0, st1, wih0, whh0);
    lstm_pw_k<<<(BB * HH + 255) / 256, 256>>>(0, st2, bih0, bhh0);

    gates2_k<<<dim3(G4 / 128, KSPL), 128>>>(1, st1 + (size_t)BB * HH, wih1, whh1);
    lstm_pw_k<<<(BB * HH + 255) / 256, 256>>>(1, st2 + (size_t)BB * HH, bih1, bhh1);

    pred2_k<<<dim3(JJ / 128, 2), 128>>>(wpred);

    fgemm_w_k<<<dim3(BB * TT / 128, JJ / 128), 256, P_SMEM>>>(encb, pbias);

    outgemm_w_k<<<dim3(BB * TT / 128, VV / 128), 256, P_SMEM>>>(outb, out, out_elems);

    tail_k<<<(2 * BB * HH + 255) / 256, 256>>>(tlen, out, out_elems);
}